// round 11
// baseline (speedup 1.0000x reference)
#include <cuda_runtime.h>
#include <cstdint>

#define C_CLUST    64
#define NCOPY      16
#define ACC_STRIDE 17                      // global scratch: 16 dims + 1 count
#define ACC_SIZE   (C_CLUST * ACC_STRIDE)  // 1088
#define P1_WARPS   4
#define P1_BLOCKS  (148 * 3)               // 66.5KB smem/block -> 3 blocks/SM
#define P2_BLOCKS  (148 * 8)

// Scratch (no allocations allowed -> __device__ globals; zero-init at load,
// and pass1's last block re-zeroes g_acc after use for replay determinism)
__device__ float    g_acc[NCOPY][ACC_SIZE];
__device__ float    g_cnt[C_CLUST];
__device__ float    g_invCD[C_CLUST];         // 1 / (C * max(count,1))
__device__ float    g_meansT[16 * C_CLUST];   // [d][c]
__device__ float    g_var;
__device__ float    g_dist;                   // dist_loss (computed in pass1 tail)
__device__ float    g_reg;                    // reg_loss  (computed in pass1 tail)
__device__ unsigned g_ctr1 = 0;               // pass1 completion tickets
__device__ unsigned g_ctr2 = 0;               // pass2 completion tickets

__device__ __forceinline__ void red_add_f32(float* addr, float v) {
    asm volatile("red.global.add.f32 [%0], %1;" :: "l"(addr), "f"(v) : "memory");
}

// ---------------------------------------------------------------- pass 1
// Float2-lane mapping: lane = (q = lane>>3, e = lane&7). The coalesced LDG.64
// at feat2[chunk*8 + it*32 + lane] IS dims (2e,2e+1) of point chunk + it*4 + q.
// 8 hoisted unconditional LDG.64 -> deep MLP. Accumulator acc2[c][q][e]:
// each quarter owns a private slice -> collision-free, conflict-free banks.
// Per chunk: 25 MIO ops (was 49) + 9 LDG ops (was 17).
// Epilogue (last block): means + invCD + dist/reg losses + scratch re-zero.
__global__ void __launch_bounds__(128) k_pass1(const float* __restrict__ feat,
                                               const int* __restrict__ labels,
                                               int npts) {
    __shared__ float2 s_acc2[P1_WARPS][C_CLUST * 32];  // [c*32 + q*8 + e], 64KB
    __shared__ float  s_cnt[P1_WARPS][C_CLUST];        // 1KB
    __shared__ float  s_c[C_CLUST];
    __shared__ float  s_red[128];
    __shared__ bool   s_last;

    const int wid  = threadIdx.x >> 5;
    const int lane = threadIdx.x & 31;
    const int q    = lane >> 3;
    const int e    = lane & 7;
    float2* accL = s_acc2[wid] + q * 8 + e;   // + c*32 per access
    float*  cntW = s_cnt[wid];

    for (int i = threadIdx.x; i < P1_WARPS * C_CLUST * 32 * 2; i += 128)
        ((float*)s_acc2)[i] = 0.f;
    for (int i = threadIdx.x; i < P1_WARPS * C_CLUST; i += 128)
        ((float*)s_cnt)[i] = 0.f;
    __syncthreads();

    const int gw    = blockIdx.x * P1_WARPS + wid;
    const int nwarp = gridDim.x * P1_WARPS;
    const float2* feat2 = (const float2*)feat;

    for (int chunk = gw * 32; chunk + 32 <= npts; chunk += nwarp * 32) {
        int labv = labels[chunk + lane];               // 32 labels, coalesced
        const float2* fb = feat2 + (size_t)chunk * 8;
        float2 v[8];
        #pragma unroll
        for (int it = 0; it < 8; it++)                 // 8 independent LDG.64
            v[it] = fb[it * 32 + lane];

        #pragma unroll
        for (int it = 0; it < 8; it++) {
            int labm = __shfl_sync(0xffffffffu, labv, it * 4 + q);
            float2 o = accL[labm * 32];                // LDS.64, conflict-free
            o.x += v[it].x; o.y += v[it].y;
            accL[labm * 32] = o;                       // STS.64, collision-free
        }
        unsigned mm = __match_any_sync(0xffffffffu, labv);
        if ((mm & ((1u << lane) - 1u)) == 0)           // leader per distinct label
            cntW[labv] += (float)__popc(mm);
    }

    // tail (npts % 32): warp 0 of block 0, quarter-0 slice
    if (gw == 0) {
        float2* a0 = s_acc2[0];
        for (int p = npts & ~31; p < npts; p++) {
            int lb = labels[p];
            if (lane < 8) {
                float2 o = a0[lb * 32 + lane];
                float2 f = feat2[(size_t)p * 8 + lane];
                o.x += f.x; o.y += f.y;
                a0[lb * 32 + lane] = o;
            }
            if (lane == 0) s_cnt[0][lb] += 1.f;
        }
    }

    // block reduce 4 warp copies x 4 quarters -> RED flush into NCOPY copies
    __syncthreads();
    const int copy = blockIdx.x & (NCOPY - 1);
    const float* accF = (const float*)s_acc2;          // [w][c*64 + q*16 + d]
    for (int idx = threadIdx.x; idx < C_CLUST * 16; idx += 128) {
        int c = idx >> 4, d = idx & 15;
        float s = 0.f;
        #pragma unroll
        for (int w = 0; w < P1_WARPS; w++) {
            const float* b = accF + (w * C_CLUST + c) * 64 + d;
            s += b[0] + b[16] + b[32] + b[48];
        }
        red_add_f32(&g_acc[copy][c * ACC_STRIDE + d], s);
    }
    for (int c = threadIdx.x; c < C_CLUST; c += 128) {
        float s = 0.f;
        #pragma unroll
        for (int w = 0; w < P1_WARPS; w++) s += s_cnt[w][c];
        red_add_f32(&g_acc[copy][c * ACC_STRIDE + 16], s);
    }

    // ---- last-block-done: means + dist/reg losses + scratch reset ----
    __threadfence();
    if (threadIdx.x == 0)
        s_last = (atomicAdd(&g_ctr1, 1u) == (unsigned)gridDim.x - 1u);
    __syncthreads();
    if (!s_last) return;
    __threadfence();                                   // acquire all blocks' REDs

    int t = threadIdx.x;
    if (t < C_CLUST) {
        float c = 0.f;
        #pragma unroll
        for (int k = 0; k < NCOPY; k++) c += g_acc[k][t * ACC_STRIDE + 16];
        g_cnt[t] = c;
        float sc = fmaxf(c, 1.f);
        s_c[t] = sc;
        g_invCD[t] = 1.f / ((float)C_CLUST * sc);
    }
    __syncthreads();

    float* s_mm = (float*)s_acc2;                      // reuse: means [c*16+d]
    for (int idx = t; idx < C_CLUST * 16; idx += 128) {
        int c = idx >> 4, d = idx & 15;
        float s = 0.f;
        #pragma unroll
        for (int k = 0; k < NCOPY; k++) s += g_acc[k][c * ACC_STRIDE + d];
        float m = s / s_c[c];
        s_mm[c * 16 + d]     = m;
        g_meansT[d * 64 + c] = m;
    }
    __syncthreads();

    // reg loss: per-cluster norm of (mean + eps)
    float regp = 0.f;
    if (t < C_CLUST) {
        float s = 0.f;
        #pragma unroll
        for (int d = 0; d < 16; d++) {
            float v = s_mm[t * 16 + d] + 1e-8f;
            s += v * v;
        }
        regp = sqrtf(s);
    }
    // dist loss: all ordered pairs i != j (4096 pairs / 128 threads)
    float dl = 0.f;
    for (int p = t; p < C_CLUST * C_CLUST; p += 128) {
        int i = p >> 6, jj = p & 63;
        if (i != jj) {
            float s = 0.f;
            #pragma unroll
            for (int d = 0; d < 16; d++) {
                float df = s_mm[i * 16 + d] - s_mm[jj * 16 + d] + 1e-8f;
                s += df * df;
            }
            float pd = sqrtf(s);
            float h = fmaxf(3.0f - pd, 0.f);           // 2 * DELTA_DIST
            dl += h * h;
        }
    }

    s_red[t] = dl; __syncthreads();
    for (int o = 64; o > 0; o >>= 1) { if (t < o) s_red[t] += s_red[t + o]; __syncthreads(); }
    if (t == 0) g_dist = s_red[0] / (float)(C_CLUST * (C_CLUST - 1));
    __syncthreads();

    s_red[t] = regp; __syncthreads();
    for (int o = 64; o > 0; o >>= 1) { if (t < o) s_red[t] += s_red[t + o]; __syncthreads(); }
    if (t == 0) g_reg = s_red[0] / (float)C_CLUST;

    // reset scratch for the next graph replay (only this block is alive)
    for (int i = t; i < NCOPY * ACC_SIZE; i += 128)
        ((float*)g_acc)[i] = 0.f;
    if (t == 0) { g_var = 0.f; g_ctr1 = 0u; }
}

// ---------------------------------------------------------------- pass 2
// Mainloop: R7 MLP-2 body verbatim (32 regs, occ 93%). Tail: trivial combine.
__global__ void __launch_bounds__(256) k_pass2(const float4* __restrict__ feat4,
                                               const int* __restrict__ labels,
                                               int n4,
                                               float* __restrict__ out) {
    __shared__ float s_mT[16][C_CLUST + 1];
    __shared__ float s_inv[C_CLUST];
    __shared__ float s_w[8];
    __shared__ bool  s_last;

    for (int i = threadIdx.x; i < 16 * C_CLUST; i += 256)
        s_mT[i >> 6][i & 63] = g_meansT[i];
    if (threadIdx.x < C_CLUST) s_inv[threadIdx.x] = g_invCD[threadIdx.x];
    __syncthreads();

    const int lane = threadIdx.x & 31;
    const int g    = threadIdx.x & 3;
    const int d0   = g * 4;
    const int stride = gridDim.x * 512;
    float local = 0.f;

    for (int j = blockIdx.x * 512 + threadIdx.x; j - lane < n4; j += stride) {
        int  jb = j + 256;
        bool a1 = (j < n4), a2 = (jb < n4);
        float4 v1, v2;
        int l1 = 0, l2 = 0;
        if (a1) { l1 = labels[j  >> 2]; v1 = feat4[j];  }
        if (a2) { l2 = labels[jb >> 2]; v2 = feat4[jb]; }

        float p1 = 0.f, p2 = 0.f;
        if (a1) {
            float dx = v1.x - s_mT[d0 + 0][l1] + 1e-8f;
            float dy = v1.y - s_mT[d0 + 1][l1] + 1e-8f;
            float dz = v1.z - s_mT[d0 + 2][l1] + 1e-8f;
            float dw = v1.w - s_mT[d0 + 3][l1] + 1e-8f;
            p1 = fmaf(dx, dx, fmaf(dy, dy, fmaf(dz, dz, dw * dw)));
        }
        if (a2) {
            float dx = v2.x - s_mT[d0 + 0][l2] + 1e-8f;
            float dy = v2.y - s_mT[d0 + 1][l2] + 1e-8f;
            float dz = v2.z - s_mT[d0 + 2][l2] + 1e-8f;
            float dw = v2.w - s_mT[d0 + 3][l2] + 1e-8f;
            p2 = fmaf(dx, dx, fmaf(dy, dy, fmaf(dz, dz, dw * dw)));
        }
        p1 += __shfl_xor_sync(0xffffffffu, p1, 1);
        p1 += __shfl_xor_sync(0xffffffffu, p1, 2);
        p2 += __shfl_xor_sync(0xffffffffu, p2, 1);
        p2 += __shfl_xor_sync(0xffffffffu, p2, 2);
        if (g == 0) {
            if (a1) {
                float h = fmaxf(sqrtf(p1) - 0.5f, 0.f);
                local += h * h * s_inv[l1];
            }
            if (a2) {
                float h = fmaxf(sqrtf(p2) - 0.5f, 0.f);
                local += h * h * s_inv[l2];
            }
        }
    }

    #pragma unroll
    for (int o = 16; o > 0; o >>= 1)
        local += __shfl_xor_sync(0xffffffffu, local, o);
    if (lane == 0) s_w[threadIdx.x >> 5] = local;
    __syncthreads();
    if (threadIdx.x == 0) {
        float s = 0.f;
        #pragma unroll
        for (int w = 0; w < 8; w++) s += s_w[w];
        red_add_f32(&g_var, s);
    }

    // ---- last-block-done: combine + write output (trivial tail) ----
    __threadfence();
    if (threadIdx.x == 0)
        s_last = (atomicAdd(&g_ctr2, 1u) == (unsigned)gridDim.x - 1u);
    __syncthreads();
    if (!s_last) return;
    __threadfence();                                   // acquire all g_var REDs

    if (threadIdx.x == 0) {
        float var_loss  = g_var;
        float dist_loss = g_dist;
        float reg_loss  = g_reg;
        out[0] = var_loss + dist_loss + 0.001f * reg_loss;
        out[1] = var_loss;
        out[2] = dist_loss;
        out[3] = reg_loss;
        g_ctr2 = 0u;
    }
}

// ---------------------------------------------------------------- launch
extern "C" void kernel_launch(void* const* d_in, const int* in_sizes, int n_in,
                              void* d_out, int out_size) {
    const float*  feat   = (const float*)d_in[0];
    const int*    labels = (const int*)d_in[1];
    int N  = in_sizes[1];     // number of points
    int n4 = N * 4;           // float4 count (D=16)

    k_pass1<<<P1_BLOCKS, 128>>>(feat, labels, N);
    k_pass2<<<P2_BLOCKS, 256>>>((const float4*)feat, labels, n4, (float*)d_out);
}

// round 12
// speedup vs baseline: 1.1346x; 1.1346x over previous
#include <cuda_runtime.h>
#include <cstdint>

#define C_CLUST    64
#define NCOPY      16
#define ACC_STRIDE 17                      // global scratch: 16 dims + 1 count
#define ACC_SIZE   (C_CLUST * ACC_STRIDE)  // 1088
#define P1_WARPS   4
#define P1_BLOCKS  (148 * 6)               // 33KB smem -> 6 blocks/SM, 24 warps/SM
#define P2_BLOCKS  (148 * 8)

// Scratch (no allocations allowed -> __device__ globals; zero-init at load,
// and pass1's last block re-zeroes g_acc after use for replay determinism)
__device__ float    g_acc[NCOPY][ACC_SIZE];
__device__ float    g_cnt[C_CLUST];
__device__ float    g_invCD[C_CLUST];         // 1 / (C * max(count,1))
__device__ float    g_meansT[16 * C_CLUST];   // [d][c]
__device__ float    g_var;
__device__ float    g_dist;                   // dist_loss (computed in pass1 tail)
__device__ float    g_reg;                    // reg_loss  (computed in pass1 tail)
__device__ unsigned g_ctr1 = 0;               // pass1 completion tickets
__device__ unsigned g_ctr2 = 0;               // pass2 completion tickets

__device__ __forceinline__ void red_add_f32(float* addr, float v) {
    asm volatile("red.global.add.f32 [%0], %1;" :: "l"(addr), "f"(v) : "memory");
}

// ---------------------------------------------------------------- pass 1
// R10 bank-disjoint scalar scheme (lane = half*16 + d; coalesced LDG.32 at
// feat[chunk*16 + it*32 + lane] IS dim d of point 2*it+half; per-warp
// acc[64][32] with half0 -> cols 0..15, half1 -> cols 16..31: conflict-free,
// alias-free). NEW: chunk loop unrolled x2 -> 64 points, 32 hoisted
// unconditional LDG.32 + 2 label LDGs per iteration (2x in-flight bytes).
// Epilogue (last block): means + invCD + dist/reg losses + scratch re-zero.
__global__ void __launch_bounds__(128) k_pass1(const float* __restrict__ feat,
                                               const int* __restrict__ labels,
                                               int npts) {
    __shared__ float s_acc[P1_WARPS][C_CLUST * 32];   // 32 KB
    __shared__ float s_cnt[P1_WARPS][C_CLUST];
    __shared__ float s_c[C_CLUST];
    __shared__ float s_red[128];
    __shared__ bool  s_last;

    const int wid  = threadIdx.x >> 5;
    const int lane = threadIdx.x & 31;
    float* accL = s_acc[wid] + lane;     // private column: col = half*16+d = lane
    float* cntW = s_cnt[wid];

    for (int i = threadIdx.x; i < P1_WARPS * C_CLUST * 32; i += 128)
        ((float*)s_acc)[i] = 0.f;
    for (int i = threadIdx.x; i < P1_WARPS * C_CLUST; i += 128)
        ((float*)s_cnt)[i] = 0.f;
    __syncthreads();

    const int half  = lane >> 4;
    const int gw    = blockIdx.x * P1_WARPS + wid;
    const int nwarp = gridDim.x * P1_WARPS;

    for (int chunk = gw * 64; chunk + 64 <= npts; chunk += nwarp * 64) {
        // hoist everything: 2 label loads + 32 feature loads, all unconditional
        int labA = labels[chunk + lane];
        int labB = labels[chunk + 32 + lane];
        const float* fb = feat + (size_t)chunk * 16;
        float va[16], vb[16];
        #pragma unroll
        for (int it = 0; it < 16; it++) va[it] = fb[it * 32 + lane];
        #pragma unroll
        for (int it = 0; it < 16; it++) vb[it] = fb[512 + it * 32 + lane];

        #pragma unroll
        for (int it = 0; it < 16; it++) {
            int labm = __shfl_sync(0xffffffffu, labA, 2 * it + half);
            accL[labm * 32] += va[it];                // bank-disjoint, alias-free
        }
        #pragma unroll
        for (int it = 0; it < 16; it++) {
            int labm = __shfl_sync(0xffffffffu, labB, 2 * it + half);
            accL[labm * 32] += vb[it];
        }
        unsigned mA = __match_any_sync(0xffffffffu, labA);
        if ((mA & ((1u << lane) - 1u)) == 0)
            cntW[labA] += (float)__popc(mA);
        unsigned mB = __match_any_sync(0xffffffffu, labB);
        if ((mB & ((1u << lane) - 1u)) == 0)
            cntW[labB] += (float)__popc(mB);
    }

    // tail (npts % 64): warp 0 of block 0, scalar per point
    if (gw == 0) {
        float* a0 = s_acc[0];
        for (int p = npts & ~63; p < npts; p++) {
            int lb = labels[p];
            if (lane < 16) a0[lb * 32 + lane] += feat[(size_t)p * 16 + lane];
            if (lane == 0) s_cnt[0][lb] += 1.f;
        }
    }

    // block reduce 4 warp copies -> RED flush into one of NCOPY global copies
    __syncthreads();
    const int copy = blockIdx.x & (NCOPY - 1);
    for (int idx = threadIdx.x; idx < C_CLUST * 16; idx += 128) {
        int c = idx >> 4, d = idx & 15;
        float s = 0.f;
        #pragma unroll
        for (int w = 0; w < P1_WARPS; w++)
            s += s_acc[w][c * 32 + d] + s_acc[w][c * 32 + 16 + d];
        red_add_f32(&g_acc[copy][c * ACC_STRIDE + d], s);
    }
    for (int c = threadIdx.x; c < C_CLUST; c += 128) {
        float s = 0.f;
        #pragma unroll
        for (int w = 0; w < P1_WARPS; w++) s += s_cnt[w][c];
        red_add_f32(&g_acc[copy][c * ACC_STRIDE + 16], s);
    }

    // ---- last-block-done: means + dist/reg losses + scratch reset ----
    __threadfence();
    if (threadIdx.x == 0)
        s_last = (atomicAdd(&g_ctr1, 1u) == (unsigned)gridDim.x - 1u);
    __syncthreads();
    if (!s_last) return;
    __threadfence();                                  // acquire all blocks' REDs

    int t = threadIdx.x;
    if (t < C_CLUST) {
        float c = 0.f;
        #pragma unroll
        for (int k = 0; k < NCOPY; k++) c += g_acc[k][t * ACC_STRIDE + 16];
        g_cnt[t] = c;
        float sc = fmaxf(c, 1.f);
        s_c[t] = sc;
        g_invCD[t] = 1.f / ((float)C_CLUST * sc);
    }
    __syncthreads();

    float* s_mm = (float*)s_acc;                      // reuse: means [c*16+d]
    for (int idx = t; idx < C_CLUST * 16; idx += 128) {
        int c = idx >> 4, d = idx & 15;
        float s = 0.f;
        #pragma unroll
        for (int k = 0; k < NCOPY; k++) s += g_acc[k][c * ACC_STRIDE + d];
        float m = s / s_c[c];
        s_mm[c * 16 + d]     = m;
        g_meansT[d * 64 + c] = m;
    }
    __syncthreads();

    // reg loss: per-cluster norm of (mean + eps)
    float regp = 0.f;
    if (t < C_CLUST) {
        float s = 0.f;
        #pragma unroll
        for (int d = 0; d < 16; d++) {
            float v = s_mm[t * 16 + d] + 1e-8f;
            s += v * v;
        }
        regp = sqrtf(s);
    }
    // dist loss: all ordered pairs i != j (4096 pairs / 128 threads)
    float dl = 0.f;
    for (int p = t; p < C_CLUST * C_CLUST; p += 128) {
        int i = p >> 6, jj = p & 63;
        if (i != jj) {
            float s = 0.f;
            #pragma unroll
            for (int d = 0; d < 16; d++) {
                float df = s_mm[i * 16 + d] - s_mm[jj * 16 + d] + 1e-8f;
                s += df * df;
            }
            float pd = sqrtf(s);
            float h = fmaxf(3.0f - pd, 0.f);          // 2 * DELTA_DIST
            dl += h * h;
        }
    }

    s_red[t] = dl; __syncthreads();
    for (int o = 64; o > 0; o >>= 1) { if (t < o) s_red[t] += s_red[t + o]; __syncthreads(); }
    if (t == 0) g_dist = s_red[0] / (float)(C_CLUST * (C_CLUST - 1));
    __syncthreads();

    s_red[t] = regp; __syncthreads();
    for (int o = 64; o > 0; o >>= 1) { if (t < o) s_red[t] += s_red[t + o]; __syncthreads(); }
    if (t == 0) g_reg = s_red[0] / (float)C_CLUST;

    // reset scratch for the next graph replay (only this block is alive)
    for (int i = t; i < NCOPY * ACC_SIZE; i += 128)
        ((float*)g_acc)[i] = 0.f;
    if (t == 0) { g_var = 0.f; g_ctr1 = 0u; }
}

// ---------------------------------------------------------------- pass 2
// Mainloop: R7 MLP-2 body verbatim (32 regs, occ 93%). Tail: trivial combine.
__global__ void __launch_bounds__(256) k_pass2(const float4* __restrict__ feat4,
                                               const int* __restrict__ labels,
                                               int n4,
                                               float* __restrict__ out) {
    __shared__ float s_mT[16][C_CLUST + 1];
    __shared__ float s_inv[C_CLUST];
    __shared__ float s_w[8];
    __shared__ bool  s_last;

    for (int i = threadIdx.x; i < 16 * C_CLUST; i += 256)
        s_mT[i >> 6][i & 63] = g_meansT[i];
    if (threadIdx.x < C_CLUST) s_inv[threadIdx.x] = g_invCD[threadIdx.x];
    __syncthreads();

    const int lane = threadIdx.x & 31;
    const int g    = threadIdx.x & 3;
    const int d0   = g * 4;
    const int stride = gridDim.x * 512;
    float local = 0.f;

    for (int j = blockIdx.x * 512 + threadIdx.x; j - lane < n4; j += stride) {
        int  jb = j + 256;
        bool a1 = (j < n4), a2 = (jb < n4);
        float4 v1, v2;
        int l1 = 0, l2 = 0;
        if (a1) { l1 = labels[j  >> 2]; v1 = feat4[j];  }
        if (a2) { l2 = labels[jb >> 2]; v2 = feat4[jb]; }

        float p1 = 0.f, p2 = 0.f;
        if (a1) {
            float dx = v1.x - s_mT[d0 + 0][l1] + 1e-8f;
            float dy = v1.y - s_mT[d0 + 1][l1] + 1e-8f;
            float dz = v1.z - s_mT[d0 + 2][l1] + 1e-8f;
            float dw = v1.w - s_mT[d0 + 3][l1] + 1e-8f;
            p1 = fmaf(dx, dx, fmaf(dy, dy, fmaf(dz, dz, dw * dw)));
        }
        if (a2) {
            float dx = v2.x - s_mT[d0 + 0][l2] + 1e-8f;
            float dy = v2.y - s_mT[d0 + 1][l2] + 1e-8f;
            float dz = v2.z - s_mT[d0 + 2][l2] + 1e-8f;
            float dw = v2.w - s_mT[d0 + 3][l2] + 1e-8f;
            p2 = fmaf(dx, dx, fmaf(dy, dy, fmaf(dz, dz, dw * dw)));
        }
        p1 += __shfl_xor_sync(0xffffffffu, p1, 1);
        p1 += __shfl_xor_sync(0xffffffffu, p1, 2);
        p2 += __shfl_xor_sync(0xffffffffu, p2, 1);
        p2 += __shfl_xor_sync(0xffffffffu, p2, 2);
        if (g == 0) {
            if (a1) {
                float h = fmaxf(sqrtf(p1) - 0.5f, 0.f);
                local += h * h * s_inv[l1];
            }
            if (a2) {
                float h = fmaxf(sqrtf(p2) - 0.5f, 0.f);
                local += h * h * s_inv[l2];
            }
        }
    }

    #pragma unroll
    for (int o = 16; o > 0; o >>= 1)
        local += __shfl_xor_sync(0xffffffffu, local, o);
    if (lane == 0) s_w[threadIdx.x >> 5] = local;
    __syncthreads();
    if (threadIdx.x == 0) {
        float s = 0.f;
        #pragma unroll
        for (int w = 0; w < 8; w++) s += s_w[w];
        red_add_f32(&g_var, s);
    }

    // ---- last-block-done: combine + write output (trivial tail) ----
    __threadfence();
    if (threadIdx.x == 0)
        s_last = (atomicAdd(&g_ctr2, 1u) == (unsigned)gridDim.x - 1u);
    __syncthreads();
    if (!s_last) return;
    __threadfence();                                  // acquire all g_var REDs

    if (threadIdx.x == 0) {
        float var_loss  = g_var;
        float dist_loss = g_dist;
        float reg_loss  = g_reg;
        out[0] = var_loss + dist_loss + 0.001f * reg_loss;
        out[1] = var_loss;
        out[2] = dist_loss;
        out[3] = reg_loss;
        g_ctr2 = 0u;
    }
}

// ---------------------------------------------------------------- launch
extern "C" void kernel_launch(void* const* d_in, const int* in_sizes, int n_in,
                              void* d_out, int out_size) {
    const float*  feat   = (const float*)d_in[0];
    const int*    labels = (const int*)d_in[1];
    int N  = in_sizes[1];     // number of points
    int n4 = N * 4;           // float4 count (D=16)

    k_pass1<<<P1_BLOCKS, 128>>>(feat, labels, N);
    k_pass2<<<P2_BLOCKS, 256>>>((const float4*)feat, labels, n4, (float*)d_out);
}

// round 13
// speedup vs baseline: 1.1411x; 1.0057x over previous
#include <cuda_runtime.h>
#include <cstdint>

#define C_CLUST    64
#define NCOPY      16
#define ACC_STRIDE 17                      // global scratch: 16 dims + 1 count
#define ACC_SIZE   (C_CLUST * ACC_STRIDE)  // 1088
#define P1_WARPS   4
#define P1_BLOCKS  (148 * 6)               // 33KB smem -> 6 blocks/SM, 24 warps/SM
#define P2_BLOCKS  (148 * 8)

// Scratch (no allocations allowed -> __device__ globals; zero-init at load,
// and pass1's last block re-zeroes g_acc after use for replay determinism)
__device__ float    g_acc[NCOPY][ACC_SIZE];
__device__ float    g_cnt[C_CLUST];
__device__ float    g_invCD[C_CLUST];         // 1 / (C * max(count,1))
__device__ float    g_meansT[16 * C_CLUST];   // [d][c]
__device__ float    g_var;
__device__ float    g_dist;                   // dist_loss (computed in pass1 tail)
__device__ float    g_reg;                    // reg_loss  (computed in pass1 tail)
__device__ unsigned g_ctr1 = 0;               // pass1 completion tickets
__device__ unsigned g_ctr2 = 0;               // pass2 completion tickets

__device__ __forceinline__ void red_add_f32(float* addr, float v) {
    asm volatile("red.global.add.f32 [%0], %1;" :: "l"(addr), "f"(v) : "memory");
}

// ---------------------------------------------------------------- pass 1
// R10 proven mainloop: scalar-lane mapping lane = half*16 + d; the coalesced
// streaming LDG.32 at feat[chunk*16 + it*32 + lane] IS dim d of point
// (2*it + half). 16 hoisted unconditional loads -> MLP=16. Per-warp
// acc[64][32]: half0 owns cols 0..15, half1 cols 16..31 -> bank-disjoint,
// alias-free, no syncwarp.
// Epilogue (last block): means + invCD + dist/reg losses + scratch re-zero.
__global__ void __launch_bounds__(128) k_pass1(const float* __restrict__ feat,
                                               const int* __restrict__ labels,
                                               int npts) {
    __shared__ float s_acc[P1_WARPS][C_CLUST * 32];   // 32 KB
    __shared__ float s_cnt[P1_WARPS][C_CLUST];
    __shared__ float s_c[C_CLUST];
    __shared__ float s_red[128];
    __shared__ bool  s_last;

    const int wid  = threadIdx.x >> 5;
    const int lane = threadIdx.x & 31;
    float* accL = s_acc[wid] + lane;     // private column: col = half*16+d = lane
    float* cntW = s_cnt[wid];

    for (int i = threadIdx.x; i < P1_WARPS * C_CLUST * 32; i += 128)
        ((float*)s_acc)[i] = 0.f;
    for (int i = threadIdx.x; i < P1_WARPS * C_CLUST; i += 128)
        ((float*)s_cnt)[i] = 0.f;
    __syncthreads();

    const int half  = lane >> 4;
    const int gw    = blockIdx.x * P1_WARPS + wid;
    const int nwarp = gridDim.x * P1_WARPS;

    for (int chunk = gw * 32; chunk + 32 <= npts; chunk += nwarp * 32) {
        int labv = __ldcs(&labels[chunk + lane]);     // 32 labels, coalesced
        const float* fb = feat + (size_t)chunk * 16;
        float v[16];
        #pragma unroll
        for (int it = 0; it < 16; it++)               // 16 streaming LDG.32
            v[it] = __ldcs(&fb[it * 32 + lane]);

        #pragma unroll
        for (int it = 0; it < 16; it++) {
            int labm = __shfl_sync(0xffffffffu, labv, 2 * it + half);
            accL[labm * 32] += v[it];                 // bank-disjoint, alias-free
        }
        unsigned mm = __match_any_sync(0xffffffffu, labv);
        if ((mm & ((1u << lane) - 1u)) == 0)          // leader per distinct label
            cntW[labv] += (float)__popc(mm);
    }

    // tail (npts % 32): warp 0 of block 0
    if (gw == 0) {
        float* a0 = s_acc[0];
        for (int p = npts & ~31; p < npts; p++) {
            int lb = labels[p];
            if (lane < 16) a0[lb * 32 + lane] += feat[(size_t)p * 16 + lane];
            if (lane == 0) s_cnt[0][lb] += 1.f;
        }
    }

    // block reduce 4 warp copies -> RED flush into one of NCOPY global copies
    __syncthreads();
    const int copy = blockIdx.x & (NCOPY - 1);
    for (int idx = threadIdx.x; idx < C_CLUST * 16; idx += 128) {
        int c = idx >> 4, d = idx & 15;
        float s = 0.f;
        #pragma unroll
        for (int w = 0; w < P1_WARPS; w++)
            s += s_acc[w][c * 32 + d] + s_acc[w][c * 32 + 16 + d];
        red_add_f32(&g_acc[copy][c * ACC_STRIDE + d], s);
    }
    for (int c = threadIdx.x; c < C_CLUST; c += 128) {
        float s = 0.f;
        #pragma unroll
        for (int w = 0; w < P1_WARPS; w++) s += s_cnt[w][c];
        red_add_f32(&g_acc[copy][c * ACC_STRIDE + 16], s);
    }

    // ---- last-block-done: means + dist/reg losses + scratch reset ----
    __threadfence();
    if (threadIdx.x == 0)
        s_last = (atomicAdd(&g_ctr1, 1u) == (unsigned)gridDim.x - 1u);
    __syncthreads();
    if (!s_last) return;
    __threadfence();                                  // acquire all blocks' REDs

    int t = threadIdx.x;
    if (t < C_CLUST) {
        float c = 0.f;
        #pragma unroll
        for (int k = 0; k < NCOPY; k++) c += g_acc[k][t * ACC_STRIDE + 16];
        g_cnt[t] = c;
        float sc = fmaxf(c, 1.f);
        s_c[t] = sc;
        g_invCD[t] = 1.f / ((float)C_CLUST * sc);
    }
    __syncthreads();

    float* s_mm = (float*)s_acc;                      // reuse: means [c*16+d]
    for (int idx = t; idx < C_CLUST * 16; idx += 128) {
        int c = idx >> 4, d = idx & 15;
        float s = 0.f;
        #pragma unroll
        for (int k = 0; k < NCOPY; k++) s += g_acc[k][c * ACC_STRIDE + d];
        float m = s / s_c[c];
        s_mm[c * 16 + d]     = m;
        g_meansT[d * 64 + c] = m;
    }
    __syncthreads();

    // reg loss: per-cluster norm of (mean + eps)
    float regp = 0.f;
    if (t < C_CLUST) {
        float s = 0.f;
        #pragma unroll
        for (int d = 0; d < 16; d++) {
            float v = s_mm[t * 16 + d] + 1e-8f;
            s += v * v;
        }
        regp = sqrtf(s);
    }
    // dist loss: all ordered pairs i != j (4096 pairs / 128 threads)
    float dl = 0.f;
    for (int p = t; p < C_CLUST * C_CLUST; p += 128) {
        int i = p >> 6, jj = p & 63;
        if (i != jj) {
            float s = 0.f;
            #pragma unroll
            for (int d = 0; d < 16; d++) {
                float df = s_mm[i * 16 + d] - s_mm[jj * 16 + d] + 1e-8f;
                s += df * df;
            }
            float pd = sqrtf(s);
            float h = fmaxf(3.0f - pd, 0.f);          // 2 * DELTA_DIST
            dl += h * h;
        }
    }

    s_red[t] = dl; __syncthreads();
    for (int o = 64; o > 0; o >>= 1) { if (t < o) s_red[t] += s_red[t + o]; __syncthreads(); }
    if (t == 0) g_dist = s_red[0] / (float)(C_CLUST * (C_CLUST - 1));
    __syncthreads();

    s_red[t] = regp; __syncthreads();
    for (int o = 64; o > 0; o >>= 1) { if (t < o) s_red[t] += s_red[t + o]; __syncthreads(); }
    if (t == 0) g_reg = s_red[0] / (float)C_CLUST;

    // reset scratch for the next graph replay (only this block is alive)
    for (int i = t; i < NCOPY * ACC_SIZE; i += 128)
        ((float*)g_acc)[i] = 0.f;
    if (t == 0) { g_var = 0.f; g_ctr1 = 0u; }
}

// ---------------------------------------------------------------- pass 2
// Mainloop: R7 MLP-2 body (32 regs, occ 93%) with streaming loads.
// Tail: trivial combine + output write in last-done block.
__global__ void __launch_bounds__(256) k_pass2(const float4* __restrict__ feat4,
                                               const int* __restrict__ labels,
                                               int n4,
                                               float* __restrict__ out) {
    __shared__ float s_mT[16][C_CLUST + 1];
    __shared__ float s_inv[C_CLUST];
    __shared__ float s_w[8];
    __shared__ bool  s_last;

    for (int i = threadIdx.x; i < 16 * C_CLUST; i += 256)
        s_mT[i >> 6][i & 63] = g_meansT[i];
    if (threadIdx.x < C_CLUST) s_inv[threadIdx.x] = g_invCD[threadIdx.x];
    __syncthreads();

    const int lane = threadIdx.x & 31;
    const int g    = threadIdx.x & 3;
    const int d0   = g * 4;
    const int stride = gridDim.x * 512;
    float local = 0.f;

    for (int j = blockIdx.x * 512 + threadIdx.x; j - lane < n4; j += stride) {
        int  jb = j + 256;
        bool a1 = (j < n4), a2 = (jb < n4);
        float4 v1, v2;
        int l1 = 0, l2 = 0;
        if (a1) { l1 = __ldcs(&labels[j  >> 2]); v1 = __ldcs(&feat4[j]);  }
        if (a2) { l2 = __ldcs(&labels[jb >> 2]); v2 = __ldcs(&feat4[jb]); }

        float p1 = 0.f, p2 = 0.f;
        if (a1) {
            float dx = v1.x - s_mT[d0 + 0][l1] + 1e-8f;
            float dy = v1.y - s_mT[d0 + 1][l1] + 1e-8f;
            float dz = v1.z - s_mT[d0 + 2][l1] + 1e-8f;
            float dw = v1.w - s_mT[d0 + 3][l1] + 1e-8f;
            p1 = fmaf(dx, dx, fmaf(dy, dy, fmaf(dz, dz, dw * dw)));
        }
        if (a2) {
            float dx = v2.x - s_mT[d0 + 0][l2] + 1e-8f;
            float dy = v2.y - s_mT[d0 + 1][l2] + 1e-8f;
            float dz = v2.z - s_mT[d0 + 2][l2] + 1e-8f;
            float dw = v2.w - s_mT[d0 + 3][l2] + 1e-8f;
            p2 = fmaf(dx, dx, fmaf(dy, dy, fmaf(dz, dz, dw * dw)));
        }
        p1 += __shfl_xor_sync(0xffffffffu, p1, 1);
        p1 += __shfl_xor_sync(0xffffffffu, p1, 2);
        p2 += __shfl_xor_sync(0xffffffffu, p2, 1);
        p2 += __shfl_xor_sync(0xffffffffu, p2, 2);
        if (g == 0) {
            if (a1) {
                float h = fmaxf(sqrtf(p1) - 0.5f, 0.f);
                local += h * h * s_inv[l1];
            }
            if (a2) {
                float h = fmaxf(sqrtf(p2) - 0.5f, 0.f);
                local += h * h * s_inv[l2];
            }
        }
    }

    #pragma unroll
    for (int o = 16; o > 0; o >>= 1)
        local += __shfl_xor_sync(0xffffffffu, local, o);
    if (lane == 0) s_w[threadIdx.x >> 5] = local;
    __syncthreads();
    if (threadIdx.x == 0) {
        float s = 0.f;
        #pragma unroll
        for (int w = 0; w < 8; w++) s += s_w[w];
        red_add_f32(&g_var, s);
    }

    // ---- last-block-done: combine + write output (trivial tail) ----
    __threadfence();
    if (threadIdx.x == 0)
        s_last = (atomicAdd(&g_ctr2, 1u) == (unsigned)gridDim.x - 1u);
    __syncthreads();
    if (!s_last) return;
    __threadfence();                                  // acquire all g_var REDs

    if (threadIdx.x == 0) {
        float var_loss  = g_var;
        float dist_loss = g_dist;
        float reg_loss  = g_reg;
        out[0] = var_loss + dist_loss + 0.001f * reg_loss;
        out[1] = var_loss;
        out[2] = dist_loss;
        out[3] = reg_loss;
        g_ctr2 = 0u;
    }
}

// ---------------------------------------------------------------- launch
extern "C" void kernel_launch(void* const* d_in, const int* in_sizes, int n_in,
                              void* d_out, int out_size) {
    const float*  feat   = (const float*)d_in[0];
    const int*    labels = (const int*)d_in[1];
    int N  = in_sizes[1];     // number of points
    int n4 = N * 4;           // float4 count (D=16)

    k_pass1<<<P1_BLOCKS, 128>>>(feat, labels, N);
    k_pass2<<<P2_BLOCKS, 256>>>((const float4*)feat, labels, n4, (float*)d_out);
}

// round 14
// speedup vs baseline: 1.1941x; 1.0464x over previous
#include <cuda_runtime.h>
#include <cstdint>

#define C_CLUST    64
#define NCOPY      16
#define ACC_STRIDE 17                      // global scratch: 16 dims + 1 count
#define ACC_SIZE   (C_CLUST * ACC_STRIDE)  // 1088
#define P1_WARPS   4
#define P1_BLOCKS  (148 * 6)               // 33KB smem -> 6 blocks/SM, 24 warps/SM
#define P2_BLOCKS  (148 * 8)

// Scratch (no allocations allowed -> __device__ globals; zero-init at load,
// and pass1's last block re-zeroes g_acc after use for replay determinism)
__device__ float    g_acc[NCOPY][ACC_SIZE];
__device__ float    g_cnt[C_CLUST];
__device__ float    g_invCD[C_CLUST];         // 1 / (C * max(count,1))
__device__ float    g_meansT[16 * C_CLUST];   // [d][c]
__device__ float    g_var;
__device__ float    g_dist;                   // dist_loss (computed in pass1 tail)
__device__ float    g_reg;                    // reg_loss  (computed in pass1 tail)
__device__ unsigned g_ctr1 = 0;               // pass1 completion tickets
__device__ unsigned g_ctr2 = 0;               // pass2 completion tickets

__device__ __forceinline__ void red_add_f32(float* addr, float v) {
    asm volatile("red.global.add.f32 [%0], %1;" :: "l"(addr), "f"(v) : "memory");
}

// ---------------------------------------------------------------- pass 1
// R10 proven mainloop: scalar-lane mapping lane = half*16 + d; the coalesced
// LDG.32 at feat[chunk*16 + it*32 + lane] IS dim d of point (2*it + half).
// 16 hoisted unconditional loads -> MLP=16. Per-warp acc[64][32]: half0 owns
// cols 0..15, half1 cols 16..31 -> bank-disjoint, alias-free, no syncwarp.
// Default cache policy so the TAIL of the stream stays resident in L2 for
// pass2's reverse-order reads.
// Epilogue (last block): means + invCD + dist/reg losses + scratch re-zero.
__global__ void __launch_bounds__(128) k_pass1(const float* __restrict__ feat,
                                               const int* __restrict__ labels,
                                               int npts) {
    __shared__ float s_acc[P1_WARPS][C_CLUST * 32];   // 32 KB
    __shared__ float s_cnt[P1_WARPS][C_CLUST];
    __shared__ float s_c[C_CLUST];
    __shared__ float s_red[128];
    __shared__ bool  s_last;

    const int wid  = threadIdx.x >> 5;
    const int lane = threadIdx.x & 31;
    float* accL = s_acc[wid] + lane;     // private column: col = half*16+d = lane
    float* cntW = s_cnt[wid];

    for (int i = threadIdx.x; i < P1_WARPS * C_CLUST * 32; i += 128)
        ((float*)s_acc)[i] = 0.f;
    for (int i = threadIdx.x; i < P1_WARPS * C_CLUST; i += 128)
        ((float*)s_cnt)[i] = 0.f;
    __syncthreads();

    const int half  = lane >> 4;
    const int gw    = blockIdx.x * P1_WARPS + wid;
    const int nwarp = gridDim.x * P1_WARPS;

    for (int chunk = gw * 32; chunk + 32 <= npts; chunk += nwarp * 32) {
        int labv = labels[chunk + lane];              // 32 labels, coalesced
        const float* fb = feat + (size_t)chunk * 16;
        float v[16];
        #pragma unroll
        for (int it = 0; it < 16; it++)               // 16 independent LDG.32
            v[it] = fb[it * 32 + lane];

        #pragma unroll
        for (int it = 0; it < 16; it++) {
            int labm = __shfl_sync(0xffffffffu, labv, 2 * it + half);
            accL[labm * 32] += v[it];                 // bank-disjoint, alias-free
        }
        unsigned mm = __match_any_sync(0xffffffffu, labv);
        if ((mm & ((1u << lane) - 1u)) == 0)          // leader per distinct label
            cntW[labv] += (float)__popc(mm);
    }

    // tail (npts % 32): warp 0 of block 0
    if (gw == 0) {
        float* a0 = s_acc[0];
        for (int p = npts & ~31; p < npts; p++) {
            int lb = labels[p];
            if (lane < 16) a0[lb * 32 + lane] += feat[(size_t)p * 16 + lane];
            if (lane == 0) s_cnt[0][lb] += 1.f;
        }
    }

    // block reduce 4 warp copies -> RED flush into one of NCOPY global copies
    __syncthreads();
    const int copy = blockIdx.x & (NCOPY - 1);
    for (int idx = threadIdx.x; idx < C_CLUST * 16; idx += 128) {
        int c = idx >> 4, d = idx & 15;
        float s = 0.f;
        #pragma unroll
        for (int w = 0; w < P1_WARPS; w++)
            s += s_acc[w][c * 32 + d] + s_acc[w][c * 32 + 16 + d];
        red_add_f32(&g_acc[copy][c * ACC_STRIDE + d], s);
    }
    for (int c = threadIdx.x; c < C_CLUST; c += 128) {
        float s = 0.f;
        #pragma unroll
        for (int w = 0; w < P1_WARPS; w++) s += s_cnt[w][c];
        red_add_f32(&g_acc[copy][c * ACC_STRIDE + 16], s);
    }

    // ---- last-block-done: means + dist/reg losses + scratch reset ----
    __threadfence();
    if (threadIdx.x == 0)
        s_last = (atomicAdd(&g_ctr1, 1u) == (unsigned)gridDim.x - 1u);
    __syncthreads();
    if (!s_last) return;
    __threadfence();                                  // acquire all blocks' REDs

    int t = threadIdx.x;
    if (t < C_CLUST) {
        float c = 0.f;
        #pragma unroll
        for (int k = 0; k < NCOPY; k++) c += g_acc[k][t * ACC_STRIDE + 16];
        g_cnt[t] = c;
        float sc = fmaxf(c, 1.f);
        s_c[t] = sc;
        g_invCD[t] = 1.f / ((float)C_CLUST * sc);
    }
    __syncthreads();

    float* s_mm = (float*)s_acc;                      // reuse: means [c*16+d]
    for (int idx = t; idx < C_CLUST * 16; idx += 128) {
        int c = idx >> 4, d = idx & 15;
        float s = 0.f;
        #pragma unroll
        for (int k = 0; k < NCOPY; k++) s += g_acc[k][c * ACC_STRIDE + d];
        float m = s / s_c[c];
        s_mm[c * 16 + d]     = m;
        g_meansT[d * 64 + c] = m;
    }
    __syncthreads();

    // reg loss: per-cluster norm of (mean + eps)
    float regp = 0.f;
    if (t < C_CLUST) {
        float s = 0.f;
        #pragma unroll
        for (int d = 0; d < 16; d++) {
            float v = s_mm[t * 16 + d] + 1e-8f;
            s += v * v;
        }
        regp = sqrtf(s);
    }
    // dist loss: all ordered pairs i != j (4096 pairs / 128 threads)
    float dl = 0.f;
    for (int p = t; p < C_CLUST * C_CLUST; p += 128) {
        int i = p >> 6, jj = p & 63;
        if (i != jj) {
            float s = 0.f;
            #pragma unroll
            for (int d = 0; d < 16; d++) {
                float df = s_mm[i * 16 + d] - s_mm[jj * 16 + d] + 1e-8f;
                s += df * df;
            }
            float pd = sqrtf(s);
            float h = fmaxf(3.0f - pd, 0.f);          // 2 * DELTA_DIST
            dl += h * h;
        }
    }

    s_red[t] = dl; __syncthreads();
    for (int o = 64; o > 0; o >>= 1) { if (t < o) s_red[t] += s_red[t + o]; __syncthreads(); }
    if (t == 0) g_dist = s_red[0] / (float)(C_CLUST * (C_CLUST - 1));
    __syncthreads();

    s_red[t] = regp; __syncthreads();
    for (int o = 64; o > 0; o >>= 1) { if (t < o) s_red[t] += s_red[t + o]; __syncthreads(); }
    if (t == 0) g_reg = s_red[0] / (float)C_CLUST;

    // reset scratch for the next graph replay (only this block is alive)
    for (int i = t; i < NCOPY * ACC_SIZE; i += 128)
        ((float*)g_acc)[i] = 0.f;
    if (t == 0) { g_var = 0.f; g_ctr1 = 0u; }
}

// ---------------------------------------------------------------- pass 2
// Mainloop: R7 MLP-2 body, but iterating chunks in DESCENDING order so the
// first ~120MB read hits the L2 lines pass1 just left resident (L2 is not
// flushed across launches). Tail: trivial combine + output write.
__global__ void __launch_bounds__(256) k_pass2(const float4* __restrict__ feat4,
                                               const int* __restrict__ labels,
                                               int n4,
                                               float* __restrict__ out) {
    __shared__ float s_mT[16][C_CLUST + 1];
    __shared__ float s_inv[C_CLUST];
    __shared__ float s_w[8];
    __shared__ bool  s_last;

    for (int i = threadIdx.x; i < 16 * C_CLUST; i += 256)
        s_mT[i >> 6][i & 63] = g_meansT[i];
    if (threadIdx.x < C_CLUST) s_inv[threadIdx.x] = g_invCD[threadIdx.x];
    __syncthreads();

    const int lane = threadIdx.x & 31;
    const int g    = threadIdx.x & 3;
    const int d0   = g * 4;
    const int nblk = (n4 + 511) >> 9;        // 512-float4 super-chunks
    float local = 0.f;

    // descending grid-stride over super-chunks (reverse of pass1's order)
    for (int cb = nblk - 1 - blockIdx.x; cb >= 0; cb -= gridDim.x) {
        int  j  = cb * 512 + threadIdx.x;
        int  jb = j + 256;
        bool a1 = (j < n4), a2 = (jb < n4);
        float4 v1, v2;
        int l1 = 0, l2 = 0;
        if (a1) { l1 = labels[j  >> 2]; v1 = feat4[j];  }
        if (a2) { l2 = labels[jb >> 2]; v2 = feat4[jb]; }

        float p1 = 0.f, p2 = 0.f;
        if (a1) {
            float dx = v1.x - s_mT[d0 + 0][l1] + 1e-8f;
            float dy = v1.y - s_mT[d0 + 1][l1] + 1e-8f;
            float dz = v1.z - s_mT[d0 + 2][l1] + 1e-8f;
            float dw = v1.w - s_mT[d0 + 3][l1] + 1e-8f;
            p1 = fmaf(dx, dx, fmaf(dy, dy, fmaf(dz, dz, dw * dw)));
        }
        if (a2) {
            float dx = v2.x - s_mT[d0 + 0][l2] + 1e-8f;
            float dy = v2.y - s_mT[d0 + 1][l2] + 1e-8f;
            float dz = v2.z - s_mT[d0 + 2][l2] + 1e-8f;
            float dw = v2.w - s_mT[d0 + 3][l2] + 1e-8f;
            p2 = fmaf(dx, dx, fmaf(dy, dy, fmaf(dz, dz, dw * dw)));
        }
        p1 += __shfl_xor_sync(0xffffffffu, p1, 1);
        p1 += __shfl_xor_sync(0xffffffffu, p1, 2);
        p2 += __shfl_xor_sync(0xffffffffu, p2, 1);
        p2 += __shfl_xor_sync(0xffffffffu, p2, 2);
        if (g == 0) {
            if (a1) {
                float h = fmaxf(sqrtf(p1) - 0.5f, 0.f);
                local += h * h * s_inv[l1];
            }
            if (a2) {
                float h = fmaxf(sqrtf(p2) - 0.5f, 0.f);
                local += h * h * s_inv[l2];
            }
        }
    }

    #pragma unroll
    for (int o = 16; o > 0; o >>= 1)
        local += __shfl_xor_sync(0xffffffffu, local, o);
    if (lane == 0) s_w[threadIdx.x >> 5] = local;
    __syncthreads();
    if (threadIdx.x == 0) {
        float s = 0.f;
        #pragma unroll
        for (int w = 0; w < 8; w++) s += s_w[w];
        red_add_f32(&g_var, s);
    }

    // ---- last-block-done: combine + write output (trivial tail) ----
    __threadfence();
    if (threadIdx.x == 0)
        s_last = (atomicAdd(&g_ctr2, 1u) == (unsigned)gridDim.x - 1u);
    __syncthreads();
    if (!s_last) return;
    __threadfence();                                  // acquire all g_var REDs

    if (threadIdx.x == 0) {
        float var_loss  = g_var;
        float dist_loss = g_dist;
        float reg_loss  = g_reg;
        out[0] = var_loss + dist_loss + 0.001f * reg_loss;
        out[1] = var_loss;
        out[2] = dist_loss;
        out[3] = reg_loss;
        g_ctr2 = 0u;
    }
}

// ---------------------------------------------------------------- launch
extern "C" void kernel_launch(void* const* d_in, const int* in_sizes, int n_in,
                              void* d_out, int out_size) {
    const float*  feat   = (const float*)d_in[0];
    const int*    labels = (const int*)d_in[1];
    int N  = in_sizes[1];     // number of points
    int n4 = N * 4;           // float4 count (D=16)

    k_pass1<<<P1_BLOCKS, 128>>>(feat, labels, N);
    k_pass2<<<P2_BLOCKS, 256>>>((const float4*)feat, labels, n4, (float*)d_out);
}